// round 1
// baseline (speedup 1.0000x reference)
#include <cuda_runtime.h>

#define B   256
#define T   2048
#define HID 128
#define ATT 8

#define SPLIT 8                    // CTAs per batch
#define CHUNK (T / SPLIT)          // 256 rows per CTA
#define NW 8                       // warps per CTA
#define THREADS (NW * 32)          // 256
#define ROWS_PER_WARP (CHUNK / NW) // 32

// scratch (no cudaMalloc allowed)
__device__ float g_partial_v[B * SPLIT * HID];
__device__ float g_partial_s[B * SPLIT];

__global__ void __launch_bounds__(THREADS)
mata_pass1(const float* __restrict__ H,
           const float* __restrict__ mask,
           const float* __restrict__ Wt,
           const float* __restrict__ Wx,
           const float* __restrict__ rate,
           const float* __restrict__ obs_bias,
           const float* __restrict__ miss_bias,
           float* __restrict__ a_out)
{
    __shared__ float  s_q[ATT];
    __shared__ __align__(16) float s_p[HID];
    __shared__ float  s_w[CHUNK];            // CHUNK == THREADS
    __shared__ __align__(16) float s_vred[NW][HID];
    __shared__ float  s_sred[NW];

    const int bx   = blockIdx.x;
    const int b    = bx / SPLIT;
    const int c    = bx % SPLIT;
    const int tid  = threadIdx.x;
    const int wid  = tid >> 5;
    const int lane = tid & 31;

    const float* Hb = H + (size_t)b * T * HID;

    // ---- q[a] = H[b, T-1, :] . Wt[:, a]  (warp 0 only) ----
    if (wid == 0) {
        const float4 hv = ((const float4*)(Hb + (size_t)(T - 1) * HID))[lane];
        const int h0 = lane * 4;
        float qa[ATT];
        #pragma unroll
        for (int a = 0; a < ATT; a++) {
            float v = hv.x * Wt[(h0 + 0) * ATT + a]
                    + hv.y * Wt[(h0 + 1) * ATT + a]
                    + hv.z * Wt[(h0 + 2) * ATT + a]
                    + hv.w * Wt[(h0 + 3) * ATT + a];
            #pragma unroll
            for (int off = 16; off > 0; off >>= 1)
                v += __shfl_xor_sync(0xffffffffu, v, off);
            qa[a] = v;
        }
        if (lane == 0) {
            #pragma unroll
            for (int a = 0; a < ATT; a++) s_q[a] = qa[a];
        }
    }
    __syncthreads();

    // ---- p[h] = sum_a Wx[h,a] * q[a] ----
    if (tid < HID) {
        float v = 0.f;
        #pragma unroll
        for (int a = 0; a < ATT; a++) v += Wx[tid * ATT + a] * s_q[a];
        s_p[tid] = v;
    }
    __syncthreads();

    const float4 pv = ((const float4*)s_p)[lane];

    const float sr = 1.f / (1.f + __expf(-rate[0]));
    const float ob = obs_bias[0];
    const float mb = miss_bias[0];

    // ---- main streaming loop: each warp owns 32 contiguous rows ----
    const int t0 = c * CHUNK + wid * ROWS_PER_WARP;
    const float* __restrict__ mrow = mask + (size_t)b * T;

    float4 acc  = make_float4(0.f, 0.f, 0.f, 0.f);
    float  sumw = 0.f;

    #pragma unroll 4
    for (int i = 0; i < ROWS_PER_WARP; i++) {
        const int t = t0 + i;
        const float4 hv = ((const float4*)(Hb + (size_t)t * HID))[lane];
        float d = hv.x * pv.x + hv.y * pv.y + hv.z * pv.z + hv.w * pv.w;
        #pragma unroll
        for (int off = 16; off > 0; off >>= 1)
            d += __shfl_xor_sync(0xffffffffu, d, off);

        const float s   = 1.f / (1.f + __expf(-d));
        const float bt  = (float)(T - t);
        const float den = sr * (__logf(2.72f + (1.f - s)) * bt);
        const float e   = fmaxf(s / den, 0.f);
        const float m   = __ldg(mrow + t);
        const float w   = __expf(e + (m > 0.5f ? ob : mb));

        acc.x += w * hv.x; acc.y += w * hv.y;
        acc.z += w * hv.z; acc.w += w * hv.w;
        sumw  += w;
        if (lane == 0) s_w[wid * ROWS_PER_WARP + i] = w;
    }

    // ---- reduce partial v / sumw across warps ----
    ((float4*)&s_vred[wid][0])[lane] = acc;
    if (lane == 0) s_sred[wid] = sumw;
    __syncthreads();

    if (tid < HID) {
        float v = 0.f;
        #pragma unroll
        for (int w = 0; w < NW; w++) v += s_vred[w][tid];
        g_partial_v[((size_t)b * SPLIT + c) * HID + tid] = v;
    }
    if (tid == 0) {
        float ss = 0.f;
        #pragma unroll
        for (int w = 0; w < NW; w++) ss += s_sred[w];
        g_partial_s[b * SPLIT + c] = ss;
    }

    // coalesced store of unnormalized weights (CHUNK == THREADS)
    a_out[(size_t)b * T + c * CHUNK + tid] = s_w[tid];
}

__global__ void __launch_bounds__(256)
mata_pass2(float* __restrict__ v_out, float* __restrict__ a_out)
{
    const int b   = blockIdx.x;
    const int tid = threadIdx.x;
    __shared__ float s_inv;

    if (tid == 0) {
        float ss = 0.f;
        #pragma unroll
        for (int c = 0; c < SPLIT; c++) ss += g_partial_s[b * SPLIT + c];
        s_inv = 1.f / ss;
    }
    __syncthreads();
    const float inv = s_inv;

    if (tid < HID) {
        float v = 0.f;
        #pragma unroll
        for (int c = 0; c < SPLIT; c++)
            v += g_partial_v[((size_t)b * SPLIT + c) * HID + tid];
        v_out[(size_t)b * HID + tid] = v * inv;
    }

    float* ab = a_out + (size_t)b * T;
    #pragma unroll
    for (int t = tid; t < T; t += 256) ab[t] *= inv;
}

extern "C" void kernel_launch(void* const* d_in, const int* in_sizes, int n_in,
                              void* d_out, int out_size)
{
    const float* H   = (const float*)d_in[0];
    const float* msk = (const float*)d_in[1];
    const float* Wt  = (const float*)d_in[2];
    const float* Wx  = (const float*)d_in[3];
    const float* rt  = (const float*)d_in[4];
    const float* ob  = (const float*)d_in[5];
    const float* mb  = (const float*)d_in[6];

    float* v_out = (float*)d_out;               // [B, HID]
    float* a_out = (float*)d_out + B * HID;     // [B, T]

    mata_pass1<<<B * SPLIT, THREADS>>>(H, msk, Wt, Wx, rt, ob, mb, a_out);
    mata_pass2<<<B, 256>>>(v_out, a_out);
}